// round 15
// baseline (speedup 1.0000x reference)
#include <cuda_runtime.h>
#include <cuda_bf16.h>

// LengthRegulator: B=16, T=512, D=384, target_len=4096, fp32.
// out[b, t, :] = x[b, idx(b,t), :], idx = searchsorted_right(cumsum(max(dur,1)), t),
// clamped to T-1; zero where t >= total(b).
//
// R14: BALANCED inverse run-length expansion.
//  - block owns 8 source rows -> output span [cum[J0-1], cum[J0+7]) (approx 60 rows).
//  - span split EVENLY across 8 warps (+-1 row) -> per-warp store work uniform,
//    fixing the dur[j] in [1,16] imbalance that idled half the LSU in R12/R13.
//  - each warp walks the <=8 runs intersecting its slice: ~2 source loads, then
//    pure STG.128 streaming (st.global.cs, evict-first).
//  - grid (64,16)=1024 blocks, 256 thr, 8 CTAs/SM -> fully resident single wave.

namespace {

constexpr int B  = 16;
constexpr int T  = 512;
constexpr int D  = 384;
constexpr int TL = 4096;
constexpr int D4 = D / 4;            // 96 float4 per row
constexpr int THREADS = 256;
constexpr int WARPS = THREADS / 32;  // 8
constexpr int SRC_PER_BLOCK = WARPS; // 8 source rows per block
constexpr int BLOCKS_X = T / SRC_PER_BLOCK;            // 64
constexpr int TAIL_PER_BLOCK = (TL - T) / BLOCKS_X;    // 56
constexpr int TAIL_PER_WARP = TAIL_PER_BLOCK / WARPS;  // 7

__device__ __forceinline__ void stcs4(float4* p, float4 v) {
    asm volatile("st.global.cs.v4.f32 [%0], {%1, %2, %3, %4};"
                 :: "l"(p), "f"(v.x), "f"(v.y), "f"(v.z), "f"(v.w) : "memory");
}

__global__ __launch_bounds__(THREADS, 8)
void length_regulator_kernel(const float* __restrict__ x,
                             const int* __restrict__ durations,
                             float* __restrict__ out)
{
    __shared__ int s_cum[T];
    __shared__ int s_wscan[8];

    const int b    = blockIdx.y;
    const int tid  = threadIdx.x;
    const int lane = tid & 31;
    const int w    = tid >> 5;

    // ---- inclusive scan of max(dur,1) over T=512, 2 elements per thread ----
    const int2 dp = reinterpret_cast<const int2*>(durations + b * T)[tid];
    const int d0 = (dp.x < 1) ? 1 : dp.x;
    const int d1 = (dp.y < 1) ? 1 : dp.y;

    int v = d0 + d1;
    #pragma unroll
    for (int o = 1; o < 32; o <<= 1) {
        int n = __shfl_up_sync(0xffffffffu, v, o);
        if (lane >= o) v += n;
    }
    if (lane == 31) s_wscan[w] = v;
    __syncthreads();
    if (w == 0 && lane < 8) {
        int wv = s_wscan[lane];
        #pragma unroll
        for (int o = 1; o < 8; o <<= 1) {
            int n = __shfl_up_sync(0x000000ffu, wv, o);
            if (lane >= o) wv += n;
        }
        s_wscan[lane] = wv;
    }
    __syncthreads();
    const int base = (w > 0) ? s_wscan[w - 1] : 0;
    const int c1 = base + v;
    s_cum[2 * tid]     = c1 - d1;
    s_cum[2 * tid + 1] = c1;
    __syncthreads();

    const int total = s_cum[T - 1];

    float* __restrict__ obf = out + (size_t)b * TL * D;
    float4* __restrict__ obv = reinterpret_cast<float4*>(obf);
    const float4* __restrict__ xb =
        reinterpret_cast<const float4*>(x) + (size_t)b * T * D4;

    // ---- balanced expansion: block's output span split evenly over warps ----
    const int J0 = blockIdx.x * SRC_PER_BLOCK;
    const int s0 = (J0 == 0) ? 0 : s_cum[J0 - 1];
    const int s1 = s_cum[J0 + SRC_PER_BLOCK - 1];
    const int s0c = (s0 < TL) ? s0 : TL;
    const int s1c = (s1 < TL) ? s1 : TL;
    const int span = s1c - s0c;

    if (span > 0) {
        const int L = (span + WARPS - 1) / WARPS;     // rows per warp (+-1)
        const int a    = s0c + w * L;
        const int bEnd = ((a + L) < s1c) ? (a + L) : s1c;

        if (a < bEnd) {
            // first source row whose run covers t=a (<=7 steps, warp-uniform)
            int j = J0;
            while (s_cum[j] <= a) ++j;

            int t = a;
            while (t < bEnd) {
                const float4* __restrict__ xr = xb + (size_t)j * D4 + lane;
                const float4 v0 = xr[0];
                const float4 v1 = xr[32];
                const float4 v2 = xr[64];

                const int ce = s_cum[j];
                const int re = (ce < bEnd) ? ce : bEnd;   // run end within slice
                float4* __restrict__ orow = obv + (size_t)t * D4 + lane;
                for (; t < re; ++t) {
                    stcs4(orow + 0,  v0);
                    stcs4(orow + 32, v1);
                    stcs4(orow + 64, v2);
                    orow += D4;
                }
                ++j;
            }
        }
    }

    // ---- tail zeroing: fixed candidate slice, rows >= T (total >= T always) ----
    if (total < TL) {
        const int cbase = T + blockIdx.x * TAIL_PER_BLOCK + w * TAIL_PER_WARP;
        const float4 z4 = make_float4(0.f, 0.f, 0.f, 0.f);
        #pragma unroll
        for (int q = 0; q < TAIL_PER_WARP; ++q) {
            const int r = cbase + q;          // r <= TL-1 by construction
            if (r >= total) {
                float4* __restrict__ orow = obv + (size_t)r * D4 + lane;
                stcs4(orow + 0,  z4);
                stcs4(orow + 32, z4);
                stcs4(orow + 64, z4);
            }
        }
    }
}

} // namespace

extern "C" void kernel_launch(void* const* d_in, const int* in_sizes, int n_in,
                              void* d_out, int out_size)
{
    const float* x         = (const float*)d_in[0];
    const int*   durations = (const int*)d_in[1];
    float*       out       = (float*)d_out;

    dim3 grid(BLOCKS_X, B);   // (64, 16)
    length_regulator_kernel<<<grid, THREADS>>>(x, durations, out);
}

// round 17
// speedup vs baseline: 1.0611x; 1.0611x over previous
#include <cuda_runtime.h>
#include <cuda_bf16.h>

// LengthRegulator: B=16, T=512, D=384, target_len=4096, fp32.
// out[b, t, :] = x[b, idx(b,t), :], idx = searchsorted_right(cumsum(max(dur,1)), t),
// clamped to T-1; zero where t >= total(b).
//
// R15: EXACT-FILL launch geometry. grid (74,16) = 1184 blocks = 148 SMs x 8 CTAs:
// the whole machine is occupied by construction (fill was capped at 86% before).
//  - block c owns source rows [c*512/74, (c+1)*512/74) (6-7 rows)
//  - balanced warp-span split (R14) over the block's output span
//  - reads-once run expansion, st.global.cs stores, fused in-block scan

namespace {

constexpr int B  = 16;
constexpr int T  = 512;
constexpr int D  = 384;
constexpr int TL = 4096;
constexpr int D4 = D / 4;            // 96 float4 per row
constexpr int THREADS = 256;
constexpr int WARPS = THREADS / 32;  // 8
constexpr int CHUNKS = 74;           // 74 x 16 = 1184 = 148 SMs x 8 CTAs
constexpr int TAIL = TL - T;         // 3584

__device__ __forceinline__ void stcs4(float4* p, float4 v) {
    asm volatile("st.global.cs.v4.f32 [%0], {%1, %2, %3, %4};"
                 :: "l"(p), "f"(v.x), "f"(v.y), "f"(v.z), "f"(v.w) : "memory");
}

__global__ __launch_bounds__(THREADS, 8)
void length_regulator_kernel(const float* __restrict__ x,
                             const int* __restrict__ durations,
                             float* __restrict__ out)
{
    __shared__ int s_cum[T];
    __shared__ int s_wscan[8];

    const int b    = blockIdx.y;
    const int c    = blockIdx.x;
    const int tid  = threadIdx.x;
    const int lane = tid & 31;
    const int w    = tid >> 5;

    // ---- inclusive scan of max(dur,1) over T=512, 2 elements per thread ----
    const int2 dp = reinterpret_cast<const int2*>(durations + b * T)[tid];
    const int d0 = (dp.x < 1) ? 1 : dp.x;
    const int d1 = (dp.y < 1) ? 1 : dp.y;

    int v = d0 + d1;
    #pragma unroll
    for (int o = 1; o < 32; o <<= 1) {
        int n = __shfl_up_sync(0xffffffffu, v, o);
        if (lane >= o) v += n;
    }
    if (lane == 31) s_wscan[w] = v;
    __syncthreads();
    if (w == 0 && lane < 8) {
        int wv = s_wscan[lane];
        #pragma unroll
        for (int o = 1; o < 8; o <<= 1) {
            int n = __shfl_up_sync(0x000000ffu, wv, o);
            if (lane >= o) wv += n;
        }
        s_wscan[lane] = wv;
    }
    __syncthreads();
    const int base = (w > 0) ? s_wscan[w - 1] : 0;
    const int c1 = base + v;
    s_cum[2 * tid]     = c1 - d1;
    s_cum[2 * tid + 1] = c1;
    __syncthreads();

    const int total = s_cum[T - 1];

    float4* __restrict__ obv =
        reinterpret_cast<float4*>(out + (size_t)b * TL * D);
    const float4* __restrict__ xb =
        reinterpret_cast<const float4*>(x) + (size_t)b * T * D4;

    // ---- this block's source-row range: [r0, r1) = [c*512/74, (c+1)*512/74) ----
    const int r0 = (c * 256) / 37;          // 512/74 == 256/37
    const int r1 = ((c + 1) * 256) / 37;

    // output span of those rows, clamped to TL
    const int a0raw = (r0 == 0) ? 0 : s_cum[r0 - 1];
    const int a1raw = s_cum[r1 - 1];
    const int a0 = (a0raw < TL) ? a0raw : TL;
    const int a1 = (a1raw < TL) ? a1raw : TL;
    const int span = a1 - a0;

    if (span > 0) {
        const int L = (span + WARPS - 1) / WARPS;     // rows per warp (+-1)
        const int a    = a0 + w * L;
        const int bEnd = ((a + L) < a1) ? (a + L) : a1;

        if (a < bEnd) {
            // first source row whose run covers t=a (warp-uniform walk, <=6 steps)
            int j = r0;
            while (s_cum[j] <= a) ++j;

            int t = a;
            while (t < bEnd) {
                const float4* __restrict__ xr = xb + (size_t)j * D4 + lane;
                const float4 v0 = xr[0];
                const float4 v1 = xr[32];
                const float4 v2 = xr[64];

                const int ce = s_cum[j];
                const int re = (ce < bEnd) ? ce : bEnd;   // run end within slice
                float4* __restrict__ orow = obv + (size_t)t * D4 + lane;
                for (; t < re; ++t) {
                    stcs4(orow + 0,  v0);
                    stcs4(orow + 32, v1);
                    stcs4(orow + 64, v2);
                    orow += D4;
                }
                ++j;
            }
        }
    }

    // ---- tail zeroing: rows [T + c*3584/74, T + (c+1)*3584/74) ----
    if (total < TL) {
        const int z0 = T + (c * 1792) / 37;          // 3584/74 == 1792/37
        const int z1 = T + ((c + 1) * 1792) / 37;
        const int zs = (z0 > total) ? z0 : total;    // first row to zero
        const int zn = z1 - zs;
        if (zn > 0) {
            const int Lz = (zn + WARPS - 1) / WARPS;
            const int za = zs + w * Lz;
            const int zb = ((za + Lz) < z1) ? (za + Lz) : z1;
            const float4 z4 = make_float4(0.f, 0.f, 0.f, 0.f);
            for (int r = za; r < zb; ++r) {
                float4* __restrict__ orow = obv + (size_t)r * D4 + lane;
                stcs4(orow + 0,  z4);
                stcs4(orow + 32, z4);
                stcs4(orow + 64, z4);
            }
        }
    }
}

} // namespace

extern "C" void kernel_launch(void* const* d_in, const int* in_sizes, int n_in,
                              void* d_out, int out_size)
{
    const float* x         = (const float*)d_in[0];
    const int*   durations = (const int*)d_in[1];
    float*       out       = (float*)d_out;

    dim3 grid(CHUNKS, B);   // (74, 16) = 1184 blocks = 148 x 8
    length_regulator_kernel<<<grid, THREADS>>>(x, durations, out);
}